// round 16
// baseline (speedup 1.0000x reference)
#include <cuda_runtime.h>
#include <cstdint>

#define MDIM 4096
#define NDIM 4096
#define KDIM 4096
#define BM 128
#define BN 128
#define BK 16
#define ROWF 16                          // 64B rows; LDS.128 conflict-free (phases tile banks 0..31)
#define NKT (KDIM / BK)                  // 256
#define ST 4                             // pipeline stages (power of 2)
#define NTHREADS 128                     // 4 warps, 64x64 warp tiles
#define STAGE_FLOATS (BM * ROWF)         // 2048 floats = 8KB per matrix per stage
#define SMEM_BYTES (2 * ST * STAGE_FLOATS * 4)   // 65536 B -> 2 CTAs/SM
#define NTILES ((MDIM / BM) * (NDIM / BN))       // 1024
#define GRID 296                                  // 148 SMs x 2 resident CTAs

// tf32-rounded, 4x4-transposed (per 16-float k-group) copies of X and W
__device__ __align__(1024) float g_Xtf[(size_t)MDIM * KDIM];
__device__ __align__(1024) float g_Wtf[(size_t)NDIM * KDIM];

__device__ __forceinline__ float f_rna(float x) {
    uint32_t r;
    asm volatile("cvt.rna.tf32.f32 %0, %1;" : "=r"(r) : "f"(x));
    return __uint_as_float(r);
}

__device__ __forceinline__ void cp_async16(uint32_t saddr, const float* g) {
    asm volatile("cp.async.cg.shared.global [%0], [%1], 16;" :: "r"(saddr), "l"(g));
}

// ---- pre-pass: RNA-round to tf32 AND 4x4-transpose each 16-float k-group:
//      out[4a+b] = in[4b+a]. Positions 4c..4c+3 then hold [c, c+4, c+8, c+12]
//      -> ONE LDS.128 per mma fragment row covers BOTH K=8 steps of a K=16 tile.
__global__ void __launch_bounds__(256)
cvt_perm_kernel(const float4* __restrict__ in, float4* __restrict__ out, int ngroups) {
    int i = blockIdx.x * blockDim.x + threadIdx.x;
    const int stride = gridDim.x * blockDim.x;
    for (; i < ngroups; i += stride) {
        float4 x0 = in[4 * i + 0];
        float4 x1 = in[4 * i + 1];
        float4 x2 = in[4 * i + 2];
        float4 x3 = in[4 * i + 3];
        float4 o0, o1, o2, o3;
        o0.x = f_rna(x0.x); o0.y = f_rna(x1.x); o0.z = f_rna(x2.x); o0.w = f_rna(x3.x);
        o1.x = f_rna(x0.y); o1.y = f_rna(x1.y); o1.z = f_rna(x2.y); o1.w = f_rna(x3.y);
        o2.x = f_rna(x0.z); o2.y = f_rna(x1.z); o2.z = f_rna(x2.z); o2.w = f_rna(x3.z);
        o3.x = f_rna(x0.w); o3.y = f_rna(x1.w); o3.z = f_rna(x2.w); o3.w = f_rna(x3.w);
        out[4 * i + 0] = o0;
        out[4 * i + 1] = o1;
        out[4 * i + 2] = o2;
        out[4 * i + 3] = o3;
    }
}

#define MMA_TF32(ACC, A0v, A1v, A2v, A3v, B0v, B1v)                              \
    asm volatile(                                                                 \
        "mma.sync.aligned.m16n8k8.row.col.f32.tf32.tf32.f32 "                     \
        "{%0,%1,%2,%3}, {%4,%5,%6,%7}, {%8,%9}, {%0,%1,%2,%3};"                   \
        : "+f"((ACC)[0]), "+f"((ACC)[1]), "+f"((ACC)[2]), "+f"((ACC)[3])          \
        : "r"(A0v), "r"(A1v), "r"(A2v), "r"(A3v), "r"(B0v), "r"(B1v))

__global__ __launch_bounds__(NTHREADS, 2)
void gemm_tf32_kernel(const float* __restrict__ X, const float* __restrict__ W,
                      const float* __restrict__ bias, float* __restrict__ Out) {
    extern __shared__ float smem[];
    float* As = smem;                         // [ST][BM][ROWF]
    float* Bs = smem + ST * STAGE_FLOATS;     // [ST][BN][ROWF]

    const int tid  = threadIdx.x;
    const int warp = tid >> 5;
    const int lane = tid & 31;

    const int warp_m = (warp >> 1) * 64;      // 0 or 64
    const int warp_n = (warp & 1) * 64;       // 0 or 64
    const int qrow = lane >> 2;               // 0..7
    const int qcol = lane & 3;                // 0..3

    const int grow   = tid >> 2;              // 0..31 (+32 per i)
    const int gchunk = (tid & 3) * 4;
    const uint32_t as0 =
        (uint32_t)__cvta_generic_to_shared(As + grow * ROWF + gchunk);
    const uint32_t bs0 =
        (uint32_t)__cvta_generic_to_shared(Bs + grow * ROWF + gchunk);
    const uint32_t stage_bytes = STAGE_FLOATS * 4;

#pragma unroll 1
    for (int t = blockIdx.x; t < NTILES; t += GRID) {
        const int bm = t >> 5;
        const int bn = t & 31;

        const float* xg = X + (size_t)(bm * BM + grow) * KDIM + gchunk;
        const float* wg = W + (size_t)(bn * BN + grow) * KDIM + gchunk;

        float acc[4][8][4];
#pragma unroll
        for (int mi = 0; mi < 4; mi++)
#pragma unroll
            for (int ni = 0; ni < 8; ni++)
#pragma unroll
                for (int r = 0; r < 4; r++) acc[mi][ni][r] = 0.0f;

        // prologue: stages 0..ST-2
#pragma unroll
        for (int s = 0; s < ST - 1; s++) {
            const float* xp = xg + (size_t)s * BK;
            const float* wp = wg + (size_t)s * BK;
            const uint32_t off = s * stage_bytes;
#pragma unroll
            for (int i = 0; i < 4; i++) {
                cp_async16(as0 + off + i * (32 * ROWF * 4), xp + (size_t)i * 32 * KDIM);
                cp_async16(bs0 + off + i * (32 * ROWF * 4), wp + (size_t)i * 32 * KDIM);
            }
            asm volatile("cp.async.commit_group;");
        }

#pragma unroll 1
        for (int kb = 0; kb < NKT; kb++) {
            const int snext = kb + ST - 1;
            if (snext < NKT) {
                asm volatile("cp.async.wait_group 2;");
            } else {
                asm volatile("cp.async.wait_group 0;");
            }
            __syncthreads();

            if (snext < NKT) {
                const float* xp = xg + (size_t)snext * BK;
                const float* wp = wg + (size_t)snext * BK;
                const uint32_t off = (snext & (ST - 1)) * stage_bytes;
#pragma unroll
                for (int i = 0; i < 4; i++) {
                    cp_async16(as0 + off + i * (32 * ROWF * 4),
                               xp + (size_t)i * 32 * KDIM);
                    cp_async16(bs0 + off + i * (32 * ROWF * 4),
                               wp + (size_t)i * 32 * KDIM);
                }
                asm volatile("cp.async.commit_group;");
            }

            const int s = kb & (ST - 1);
            const float* A0 = As + s * STAGE_FLOATS + (warp_m + qrow) * ROWF + 4 * qcol;
            const float* B0 = Bs + s * STAGE_FLOATS + (warp_n + qrow) * ROWF + 4 * qcol;

            // A fragments: one LDS.128 per row pair covers both K=8 steps
            // aLo: [a0k0, a2k0, a0k1, a2k1], aHi: [a1k0, a3k0, a1k1, a3k1]
            uint4 aLo[4], aHi[4];
#pragma unroll
            for (int mi = 0; mi < 4; mi++) {
                aLo[mi] = *reinterpret_cast<const uint4*>(A0 + mi * 16 * ROWF);
                aHi[mi] = *reinterpret_cast<const uint4*>(A0 + (mi * 16 + 8) * ROWF);
            }

            // B in two ni-halves of 4 to cap live registers
#pragma unroll
            for (int h = 0; h < 2; h++) {
                uint4 bF[4];
#pragma unroll
                for (int nj = 0; nj < 4; nj++)
                    bF[nj] = *reinterpret_cast<const uint4*>(
                        B0 + ((h * 4 + nj) * 8) * ROWF);
#pragma unroll
                for (int mi = 0; mi < 4; mi++)
#pragma unroll
                    for (int nj = 0; nj < 4; nj++) {
                        MMA_TF32(acc[mi][h * 4 + nj],
                                 aLo[mi].x, aHi[mi].x, aLo[mi].y, aHi[mi].y,
                                 bF[nj].x, bF[nj].y);
                        MMA_TF32(acc[mi][h * 4 + nj],
                                 aLo[mi].z, aHi[mi].z, aLo[mi].w, aHi[mi].w,
                                 bF[nj].z, bF[nj].w);
                    }
            }
        }

        // ---- epilogue: bias add + float2 stores (overlaps peer CTA's mainloop)
        const int row0 = bm * BM + warp_m + qrow;
        const int col0 = bn * BN + warp_n + 2 * qcol;

        float2 bv[8];
#pragma unroll
        for (int ni = 0; ni < 8; ni++) {
            bv[ni].x = bias[col0 + ni * 8];
            bv[ni].y = bias[col0 + ni * 8 + 1];
        }

#pragma unroll
        for (int mi = 0; mi < 4; mi++) {
            const int r = row0 + mi * 16;
#pragma unroll
            for (int ni = 0; ni < 8; ni++) {
                const int c = col0 + ni * 8;
                float2 v0 = make_float2(acc[mi][ni][0] + bv[ni].x,
                                        acc[mi][ni][1] + bv[ni].y);
                float2 v1 = make_float2(acc[mi][ni][2] + bv[ni].x,
                                        acc[mi][ni][3] + bv[ni].y);
                *reinterpret_cast<float2*>(&Out[(size_t)r * NDIM + c]) = v0;
                *reinterpret_cast<float2*>(&Out[(size_t)(r + 8) * NDIM + c]) = v1;
            }
        }
        // next iteration's wait+__syncthreads orders prologue writes against
        // this tile's last-stage reads (only ST-1 stages are refilled early).
    }
}

extern "C" void kernel_launch(void* const* d_in, const int* in_sizes, int n_in,
                              void* d_out, int out_size) {
    const float* x    = (const float*)d_in[0];
    const float* w    = (const float*)d_in[1];
    const float* bias = (const float*)d_in[2];
    float* out        = (float*)d_out;

    void* pX = nullptr; void* pW = nullptr;
    cudaGetSymbolAddress(&pX, g_Xtf);
    cudaGetSymbolAddress(&pW, g_Wtf);

    const int ngroups = (MDIM * KDIM) / 16;   // 16-float k-groups per matrix
    cvt_perm_kernel<<<4096, 256>>>((const float4*)x, (float4*)pX, ngroups);
    cvt_perm_kernel<<<4096, 256>>>((const float4*)w, (float4*)pW, ngroups);

    cudaFuncSetAttribute(gemm_tf32_kernel,
                         cudaFuncAttributeMaxDynamicSharedMemorySize, SMEM_BYTES);

    gemm_tf32_kernel<<<GRID, NTHREADS, SMEM_BYTES>>>((const float*)pX, (const float*)pW,
                                                     bias, out);
}

// round 17
// speedup vs baseline: 1.7127x; 1.7127x over previous
#include <cuda_runtime.h>
#include <cstdint>

#define MDIM 4096
#define NDIM 4096
#define KDIM 4096
#define BM 128
#define BN 128
#define BK 32
#define ROWF 40                          // 160B rows; LDS.64 + cp.async provably conflict-free
#define NKT (KDIM / BK)                  // 128
#define ST 2                             // double buffer
#define NTHREADS 128                     // 4 warps, 64x64 warp tiles
#define STAGE_FLOATS (BM * ROWF)         // 5120 floats = 20KB per matrix per stage
#define SMEM_BYTES (2 * ST * STAGE_FLOATS * 4)   // 81920 B -> 2 CTAs/SM
#define NTILES ((MDIM / BM) * (NDIM / BN))       // 1024
#define GRID 296                                  // 148 SMs x 2 resident CTAs

// tf32-rounded, k-permuted copies of X and W (static device scratch)
__device__ __align__(1024) float g_Xtf[(size_t)MDIM * KDIM];
__device__ __align__(1024) float g_Wtf[(size_t)NDIM * KDIM];

__device__ __forceinline__ float f_rna(float x) {
    uint32_t r;
    asm volatile("cvt.rna.tf32.f32 %0, %1;" : "=r"(r) : "f"(x));
    return __uint_as_float(r);
}

__device__ __forceinline__ void cp_async16(uint32_t saddr, const float* g) {
    asm volatile("cp.async.cg.shared.global [%0], [%1], 16;" :: "r"(saddr), "l"(g));
}

// ---- pre-pass: RNA-round to tf32 AND permute each 8-float k-group to
//      [0,4,1,5,2,6,3,7] so each mma fragment (col, col+4) pair is one LDS.64.
//      (identical to R15 — validated layout)
__global__ void __launch_bounds__(256)
cvt_perm_kernel(const float4* __restrict__ in, float4* __restrict__ out, int ngroups) {
    int i = blockIdx.x * blockDim.x + threadIdx.x;
    const int stride = gridDim.x * blockDim.x;
    for (; i < ngroups; i += stride) {
        float4 x0 = in[2 * i];
        float4 x1 = in[2 * i + 1];
        float4 o0, o1;
        o0.x = f_rna(x0.x); o0.y = f_rna(x1.x);
        o0.z = f_rna(x0.y); o0.w = f_rna(x1.y);
        o1.x = f_rna(x0.z); o1.y = f_rna(x1.z);
        o1.z = f_rna(x0.w); o1.w = f_rna(x1.w);
        out[2 * i]     = o0;
        out[2 * i + 1] = o1;
    }
}

#define MMA_TF32(ACC, ALO, AHI, B)                                              \
    asm volatile(                                                                \
        "mma.sync.aligned.m16n8k8.row.col.f32.tf32.tf32.f32 "                    \
        "{%0,%1,%2,%3}, {%4,%5,%6,%7}, {%8,%9}, {%0,%1,%2,%3};"                  \
        : "+f"((ACC)[0]), "+f"((ACC)[1]), "+f"((ACC)[2]), "+f"((ACC)[3])         \
        : "r"((ALO).x), "r"((AHI).x), "r"((ALO).y), "r"((AHI).y),                \
          "r"((B).x), "r"((B).y))

__global__ __launch_bounds__(NTHREADS, 2)
void gemm_tf32_kernel(const float* __restrict__ X, const float* __restrict__ W,
                      const float* __restrict__ bias, float* __restrict__ Out) {
    extern __shared__ float smem[];
    float* As = smem;                         // [ST][BM][ROWF]
    float* Bs = smem + ST * STAGE_FLOATS;     // [ST][BN][ROWF]

    const int tid  = threadIdx.x;
    const int warp = tid >> 5;
    const int lane = tid & 31;

    const int warp_m = (warp >> 1) * 64;      // 0 or 64
    const int warp_n = (warp & 1) * 64;       // 0 or 64
    const int qrow = lane >> 2;               // 0..7
    const int qcol = lane & 3;                // 0..3

    // global->shared: 128 rows x 8 x 16B chunks; thread: row=tid>>3 (+16*i), chunk=tid&7
    const int grow   = tid >> 3;              // 0..15 (+16 per i, 8 iters)
    const int gchunk = (tid & 7) * 4;
    const uint32_t as0 =
        (uint32_t)__cvta_generic_to_shared(As + grow * ROWF + gchunk);
    const uint32_t bs0 =
        (uint32_t)__cvta_generic_to_shared(Bs + grow * ROWF + gchunk);
    const uint32_t stage_bytes = STAGE_FLOATS * 4;   // 20480

#pragma unroll 1
    for (int t = blockIdx.x; t < NTILES; t += GRID) {
        const int bm = t >> 5;
        const int bn = t & 31;

        const float* xg = X + (size_t)(bm * BM + grow) * KDIM + gchunk;
        const float* wg = W + (size_t)(bn * BN + grow) * KDIM + gchunk;

        float acc[4][8][4];
#pragma unroll
        for (int mi = 0; mi < 4; mi++)
#pragma unroll
            for (int ni = 0; ni < 8; ni++)
#pragma unroll
                for (int r = 0; r < 4; r++) acc[mi][ni][r] = 0.0f;

        // prologue: stage 0
        {
#pragma unroll
            for (int i = 0; i < 8; i++) {
                cp_async16(as0 + i * (16 * ROWF * 4), xg + (size_t)i * 16 * KDIM);
                cp_async16(bs0 + i * (16 * ROWF * 4), wg + (size_t)i * 16 * KDIM);
            }
            asm volatile("cp.async.commit_group;");
        }

#pragma unroll 1
        for (int kb = 0; kb < NKT; kb++) {
            asm volatile("cp.async.wait_group 0;");
            __syncthreads();

            const int snext = kb + 1;
            if (snext < NKT) {
                const float* xp = xg + (size_t)snext * BK;
                const float* wp = wg + (size_t)snext * BK;
                const uint32_t off = (snext & 1) * stage_bytes;
#pragma unroll
                for (int i = 0; i < 8; i++) {
                    cp_async16(as0 + off + i * (16 * ROWF * 4),
                               xp + (size_t)i * 16 * KDIM);
                    cp_async16(bs0 + off + i * (16 * ROWF * 4),
                               wp + (size_t)i * 16 * KDIM);
                }
                asm volatile("cp.async.commit_group;");
            }

            const int s = kb & 1;
            const float* A0 = As + s * STAGE_FLOATS + warp_m * ROWF;
            const float* B0 = Bs + s * STAGE_FLOATS + warp_n * ROWF;

            uint2 alo[2][4], ahi[2][4], bb[2][8];
            // load k-step 0 fragments (group offset 0)
#pragma unroll
            for (int mi = 0; mi < 4; mi++) {
                const float* ap = A0 + (mi * 16 + qrow) * ROWF;
                alo[0][mi] = reinterpret_cast<const uint2*>(ap)[qcol];
                ahi[0][mi] = reinterpret_cast<const uint2*>(ap + 8 * ROWF)[qcol];
            }
#pragma unroll
            for (int ni = 0; ni < 8; ni++) {
                const float* bp = B0 + (ni * 8 + qrow) * ROWF;
                bb[0][ni] = reinterpret_cast<const uint2*>(bp)[qcol];
            }

#pragma unroll
            for (int kk = 0; kk < 4; kk++) {
                const int cur = kk & 1;
                if (kk < 3) {   // prefetch k-step kk+1 (group offset 8*(kk+1) floats)
                    const int nxt = cur ^ 1;
                    const int go = 8 * (kk + 1);
#pragma unroll
                    for (int mi = 0; mi < 4; mi++) {
                        const float* ap = A0 + (mi * 16 + qrow) * ROWF + go;
                        alo[nxt][mi] = reinterpret_cast<const uint2*>(ap)[qcol];
                        ahi[nxt][mi] = reinterpret_cast<const uint2*>(ap + 8 * ROWF)[qcol];
                    }
#pragma unroll
                    for (int ni = 0; ni < 8; ni++) {
                        const float* bp = B0 + (ni * 8 + qrow) * ROWF + go;
                        bb[nxt][ni] = reinterpret_cast<const uint2*>(bp)[qcol];
                    }
                }
#pragma unroll
                for (int mi = 0; mi < 4; mi++)
#pragma unroll
                    for (int ni = 0; ni < 8; ni++)
                        MMA_TF32(acc[mi][ni], alo[cur][mi], ahi[cur][mi], bb[cur][ni]);
            }
        }

        // ---- epilogue: bias add + float2 stores (overlaps peer CTA's mainloop)
        const int row0 = bm * BM + warp_m + qrow;
        const int col0 = bn * BN + warp_n + 2 * qcol;

        float2 bv[8];
#pragma unroll
        for (int ni = 0; ni < 8; ni++) {
            bv[ni].x = bias[col0 + ni * 8];
            bv[ni].y = bias[col0 + ni * 8 + 1];
        }

#pragma unroll
        for (int mi = 0; mi < 4; mi++) {
            const int r = row0 + mi * 16;
#pragma unroll
            for (int ni = 0; ni < 8; ni++) {
                const int c = col0 + ni * 8;
                float2 v0 = make_float2(acc[mi][ni][0] + bv[ni].x,
                                        acc[mi][ni][1] + bv[ni].y);
                float2 v1 = make_float2(acc[mi][ni][2] + bv[ni].x,
                                        acc[mi][ni][3] + bv[ni].y);
                *reinterpret_cast<float2*>(&Out[(size_t)r * NDIM + c]) = v0;
                *reinterpret_cast<float2*>(&Out[(size_t)(r + 8) * NDIM + c]) = v1;
            }
        }
        // next tile's wait_group(0)+__syncthreads orders its prologue writes
        // against this tile's final-stage reads.
    }
}

extern "C" void kernel_launch(void* const* d_in, const int* in_sizes, int n_in,
                              void* d_out, int out_size) {
    const float* x    = (const float*)d_in[0];
    const float* w    = (const float*)d_in[1];
    const float* bias = (const float*)d_in[2];
    float* out        = (float*)d_out;

    void* pX = nullptr; void* pW = nullptr;
    cudaGetSymbolAddress(&pX, g_Xtf);
    cudaGetSymbolAddress(&pW, g_Wtf);

    const int ngroups = (MDIM * KDIM) / 8;
    cvt_perm_kernel<<<4096, 256>>>((const float4*)x, (float4*)pX, ngroups);
    cvt_perm_kernel<<<4096, 256>>>((const float4*)w, (float4*)pW, ngroups);

    cudaFuncSetAttribute(gemm_tf32_kernel,
                         cudaFuncAttributeMaxDynamicSharedMemorySize, SMEM_BYTES);

    gemm_tf32_kernel<<<GRID, NTHREADS, SMEM_BYTES>>>((const float*)pX, (const float*)pW,
                                                     bias, out);
}